// round 5
// baseline (speedup 1.0000x reference)
#include <cuda_runtime.h>
#include <math_constants.h>

#define CIN   384
#define COUT  192
#define NB    4
#define NPER  4096
#define MPER  16384
#define NTOT  (NB * NPER)   // 16384
#define MTOT  (NB * MPER)   // 65536
#define LN_EPS 1e-5f

#define GRID_R 8
#define NCELL  (GRID_R * GRID_R * GRID_R)   // 512
#define TCELL  (NB * NCELL)                 // 2048
#define CELL_H (1.0f / GRID_R)

#define ROWS   64            // rows per GEMM block
#define PITCH  68            // smem row-pitch (floats); 272B keeps 16B align, 4-way STS conflict max

typedef unsigned long long ull;

// ------------------------- static device scratch ---------------------------
__device__ float  g_h [(size_t)NTOT * COUT];
__device__ float  g_wk[(size_t)MTOT * 3];
__device__ int    g_ik[(size_t)MTOT * 3];
__device__ int    g_cnt[TCELL];
__device__ int    g_cellstart[TCELL + 1];
__device__ int    g_fill[TCELL];
__device__ float4 g_pts4[NTOT];

// ------------------------- helpers -----------------------------------------
__device__ __forceinline__ float warp_sum(float v) {
#pragma unroll
    for (int o = 16; o > 0; o >>= 1) v += __shfl_xor_sync(0xffffffffu, v, o);
    return v;
}
__device__ __forceinline__ ull pack2(float lo, float hi) {
    ull r; asm("mov.b64 %0, {%1, %2};" : "=l"(r) : "f"(lo), "f"(hi)); return r;
}
__device__ __forceinline__ void unpack2(ull v, float& lo, float& hi) {
    asm("mov.b64 {%0, %1}, %2;" : "=f"(lo), "=f"(hi) : "l"(v));
}
__device__ __forceinline__ ull ffma2(ull a, ull b, ull c) {
    ull d; asm("fma.rn.f32x2 %0, %1, %2, %3;" : "=l"(d) : "l"(a), "l"(b), "l"(c)); return d;
}
__device__ __forceinline__ int cell1(float v) {
    int c = (int)(v * GRID_R);
    return min(GRID_R - 1, max(0, c));
}
__device__ __forceinline__ void ins3(float s, int gi,
                                     float& s0, float& s1, float& s2,
                                     int& i0, int& i1, int& i2) {
    if (s < s2) {
        if (s < s1) {
            s2 = s1; i2 = i1;
            if (s < s0) { s1 = s0; i1 = i0; s0 = s; i0 = gi; }
            else        { s1 = s;  i1 = gi; }
        } else { s2 = s; i2 = gi; }
    }
}
__device__ __forceinline__ void scan_run(int lo, int hi,
                                         float qx, float qy, float qz,
                                         float& s0, float& s1, float& s2,
                                         int& i0, int& i1, int& i2) {
    int j = lo;
    for (; j + 4 <= hi; j += 4) {
        const float4 p0 = g_pts4[j];
        const float4 p1 = g_pts4[j + 1];
        const float4 p2 = g_pts4[j + 2];
        const float4 p3 = g_pts4[j + 3];
        float dx, dy, dz;
        dx = qx - p0.x; dy = qy - p0.y; dz = qz - p0.z;
        const float a0 = fmaf(dx, dx, fmaf(dy, dy, dz * dz));
        dx = qx - p1.x; dy = qy - p1.y; dz = qz - p1.z;
        const float a1 = fmaf(dx, dx, fmaf(dy, dy, dz * dz));
        dx = qx - p2.x; dy = qy - p2.y; dz = qz - p2.z;
        const float a2 = fmaf(dx, dx, fmaf(dy, dy, dz * dz));
        dx = qx - p3.x; dy = qy - p3.y; dz = qz - p3.z;
        const float a3 = fmaf(dx, dx, fmaf(dy, dy, dz * dz));
        ins3(a0, __float_as_int(p0.w), s0, s1, s2, i0, i1, i2);
        ins3(a1, __float_as_int(p1.w), s0, s1, s2, i0, i1, i2);
        ins3(a2, __float_as_int(p2.w), s0, s1, s2, i0, i1, i2);
        ins3(a3, __float_as_int(p3.w), s0, s1, s2, i0, i1, i2);
    }
    for (; j < hi; j++) {
        const float4 p = g_pts4[j];
        const float dx = qx - p.x, dy = qy - p.y, dz = qz - p.z;
        const float s = fmaf(dx, dx, fmaf(dy, dy, dz * dz));
        ins3(s, __float_as_int(p.w), s0, s1, s2, i0, i1, i2);
    }
}

// ------------------------- grid build --------------------------------------
__global__ void k_grid_zero() {
    int i = blockIdx.x * 1024 + threadIdx.x;
    if (i < TCELL) g_cnt[i] = 0;
}
__global__ __launch_bounds__(256) void k_grid_count(const float* __restrict__ xyz) {
    int i = blockIdx.x * 256 + threadIdx.x;
    int b = i >> 12;
    int cx = cell1(xyz[i * 3 + 0]);
    int cy = cell1(xyz[i * 3 + 1]);
    int cz = cell1(xyz[i * 3 + 2]);
    atomicAdd(&g_cnt[b * NCELL + (cz * GRID_R + cy) * GRID_R + cx], 1);
}
__global__ __launch_bounds__(1024) void k_grid_scan() {
    __shared__ int A[TCELL], B[TCELL];
    int t = threadIdx.x;
    A[t] = g_cnt[t];  A[t + 1024] = g_cnt[t + 1024];
    __syncthreads();
    int* src = A; int* dst = B;
    for (int off = 1; off < TCELL; off <<= 1) {
        dst[t]        = src[t]        + (t        >= off ? src[t        - off] : 0);
        dst[t + 1024] = src[t + 1024] + (t + 1024 >= off ? src[t + 1024 - off] : 0);
        __syncthreads();
        int* tmp = src; src = dst; dst = tmp;
    }
    int ex0 = (t == 0) ? 0 : src[t - 1];
    g_cellstart[t] = ex0;  g_fill[t] = ex0;
    int u = t + 1024;
    int ex1 = src[u - 1];
    g_cellstart[u] = ex1;  g_fill[u] = ex1;
    if (t == 0) g_cellstart[TCELL] = NTOT;
}
__global__ __launch_bounds__(256) void k_grid_scatter(const float* __restrict__ xyz) {
    int i = blockIdx.x * 256 + threadIdx.x;
    int b = i >> 12;
    float x = xyz[i * 3 + 0], y = xyz[i * 3 + 1], z = xyz[i * 3 + 2];
    int cid = b * NCELL + (cell1(z) * GRID_R + cell1(y)) * GRID_R + cell1(x);
    int pos = atomicAdd(&g_fill[cid], 1);
    g_pts4[pos] = make_float4(x, y, z, __int_as_float(i));
}

// ------------------------- grid 3-NN ---------------------------------------
__global__ __launch_bounds__(256) void k_knn_grid(const float* __restrict__ sxyz) {
    const int q = blockIdx.x * 256 + threadIdx.x;
    const int b = q >> 14;
    const float qx = sxyz[q * 3 + 0];
    const float qy = sxyz[q * 3 + 1];
    const float qz = sxyz[q * 3 + 2];
    const int cx = cell1(qx), cy = cell1(qy), cz = cell1(qz);
    const int base = b * NCELL;

    float s0 = CUDART_INF_F, s1 = CUDART_INF_F, s2 = CUDART_INF_F;
    int   i0 = 0, i1 = 0, i2 = 0;

    // ---- uniform pass: clamped 3x3x3 neighborhood (no divergence) ----
    {
        const int zl = max(0, cz - 1), zh = min(GRID_R - 1, cz + 1);
        const int yl = max(0, cy - 1), yh = min(GRID_R - 1, cy + 1);
        const int xl = max(0, cx - 1), xh = min(GRID_R - 1, cx + 1);
        for (int Z = zl; Z <= zh; Z++)
            for (int Y = yl; Y <= yh; Y++) {
                const int rowb = base + (Z * GRID_R + Y) * GRID_R;
                const int lo = g_cellstart[rowb + xl];
                const int hi = g_cellstart[rowb + xh + 1];
                scan_run(lo, hi, qx, qy, qz, s0, s1, s2, i0, i1, i2);
            }
    }
    // coverage radius for R=1
    float rc = CUDART_INF_F;
    if (cx - 1 > 0)          rc = fminf(rc, qx - (cx - 1) * CELL_H);
    if (cx + 1 < GRID_R - 1) rc = fminf(rc, (cx + 2) * CELL_H - qx);
    if (cy - 1 > 0)          rc = fminf(rc, qy - (cy - 1) * CELL_H);
    if (cy + 1 < GRID_R - 1) rc = fminf(rc, (cy + 2) * CELL_H - qy);
    if (cz - 1 > 0)          rc = fminf(rc, qz - (cz - 1) * CELL_H);
    if (cz + 1 < GRID_R - 1) rc = fminf(rc, (cz + 2) * CELL_H - qz);

    if (!(s2 < rc * rc)) {
        // rare expansion tail: rings R >= 2
        bool done = false;
        for (int R = 2; R < GRID_R && !done; R++) {
            const int zl = max(0, cz - R), zh = min(GRID_R - 1, cz + R);
            const int yl = max(0, cy - R), yh = min(GRID_R - 1, cy + R);
            const int xl = max(0, cx - R), xh = min(GRID_R - 1, cx + R);
            for (int Z = zl; Z <= zh; Z++) {
                const bool zedge = (Z == cz - R) || (Z == cz + R);
                for (int Y = yl; Y <= yh; Y++) {
                    const bool yedge = (Y == cy - R) || (Y == cy + R);
                    const int rowb = base + (Z * GRID_R + Y) * GRID_R;
                    if (zedge || yedge) {
                        const int lo = g_cellstart[rowb + xl];
                        const int hi = g_cellstart[rowb + xh + 1];
                        scan_run(lo, hi, qx, qy, qz, s0, s1, s2, i0, i1, i2);
                    } else {
#pragma unroll
                        for (int e = 0; e < 2; e++) {
                            const int X = (e == 0) ? (cx - R) : (cx + R);
                            if (X < 0 || X >= GRID_R) continue;
                            const int lo = g_cellstart[rowb + X];
                            const int hi = g_cellstart[rowb + X + 1];
                            scan_run(lo, hi, qx, qy, qz, s0, s1, s2, i0, i1, i2);
                        }
                    }
                }
            }
            float rcv = CUDART_INF_F;
            if (cx - R > 0)          rcv = fminf(rcv, qx - (cx - R) * CELL_H);
            if (cx + R < GRID_R - 1) rcv = fminf(rcv, (cx + R + 1) * CELL_H - qx);
            if (cy - R > 0)          rcv = fminf(rcv, qy - (cy - R) * CELL_H);
            if (cy + R < GRID_R - 1) rcv = fminf(rcv, (cy + R + 1) * CELL_H - qy);
            if (cz - R > 0)          rcv = fminf(rcv, qz - (cz - R) * CELL_H);
            if (cz + R < GRID_R - 1) rcv = fminf(rcv, (cz + R + 1) * CELL_H - qz);
            if (s2 < rcv * rcv) done = true;
        }
    }

    const float d0 = sqrtf(fmaxf(s0, 0.f));
    const float d1 = sqrtf(fmaxf(s1, 0.f));
    const float d2 = sqrtf(fmaxf(s2, 0.f));
    const float r0 = 1.0f / (d0 + 1e-8f);
    const float r1 = 1.0f / (d1 + 1e-8f);
    const float r2 = 1.0f / (d2 + 1e-8f);
    const float rs = 1.0f / (r0 + r1 + r2);
    g_wk[q * 3 + 0] = r0 * rs;  g_ik[q * 3 + 0] = i0;
    g_wk[q * 3 + 1] = r1 * rs;  g_ik[q * 3 + 1] = i1;
    g_wk[q * 3 + 2] = r2 * rs;  g_ik[q * 3 + 2] = i2;
}

// ---------------------------------------------------------------------------
// GEMM 2: h = LN(feats; ln2) @ w2 + b2   [NTOT x 384] -> [NTOT x 192]
// 192 threads, 64 rows/block, f32x2 accumulation (32 row-pairs/thread)
// ---------------------------------------------------------------------------
__global__ __launch_bounds__(192) void k_ln_gemm2(
    const float* __restrict__ feats,
    const float* __restrict__ ln_g, const float* __restrict__ ln_b,
    const float* __restrict__ w,    const float* __restrict__ bias)
{
    extern __shared__ float xs[];          // [CIN][PITCH]
    const int tid = threadIdx.x, wid = tid >> 5, lane = tid & 31;
    const int row0 = blockIdx.x * ROWS;

    for (int r = wid; r < ROWS; r += 6) {
        const float* x = feats + (size_t)(row0 + r) * CIN;
        float v[12];
        float s = 0.f, ss = 0.f;
#pragma unroll
        for (int t = 0; t < 12; t++) {
            v[t] = x[lane + 32 * t];
            s  += v[t];
            ss += v[t] * v[t];
        }
        s  = warp_sum(s);
        ss = warp_sum(ss);
        const float mu  = s * (1.0f / CIN);
        const float inv = rsqrtf(ss * (1.0f / CIN) - mu * mu + LN_EPS);
#pragma unroll
        for (int t = 0; t < 12; t++) {
            const int k = lane + 32 * t;
            xs[k * PITCH + r] = (v[t] - mu) * inv * ln_g[k] + ln_b[k];
        }
    }
    __syncthreads();

    const int j = tid;
    ull acc[ROWS / 2];
#pragma unroll
    for (int p = 0; p < ROWS / 2; p++) acc[p] = 0ull;

#pragma unroll 2
    for (int k = 0; k < CIN; k++) {
        const float wk = w[(size_t)k * COUT + j];
        const ull ww = pack2(wk, wk);
        const double2* xr = (const double2*)(xs + k * PITCH);
#pragma unroll
        for (int c = 0; c < ROWS / 4; c++) {
            const double2 d = xr[c];
            acc[2 * c]     = ffma2(__double_as_longlong(d.x), ww, acc[2 * c]);
            acc[2 * c + 1] = ffma2(__double_as_longlong(d.y), ww, acc[2 * c + 1]);
        }
    }
    const float bb = bias[j];
#pragma unroll
    for (int p = 0; p < ROWS / 2; p++) {
        float lo, hi; unpack2(acc[p], lo, hi);
        g_h[(size_t)(row0 + 2 * p)     * COUT + j] = lo + bb;
        g_h[(size_t)(row0 + 2 * p + 1) * COUT + j] = hi + bb;
    }
}

// ---------------------------------------------------------------------------
// GEMM 1: out = LN(support_feats; ln1) @ w1 + b1 + interp-gather(g_h)
// ---------------------------------------------------------------------------
__global__ __launch_bounds__(192) void k_ln_gemm1(
    const float* __restrict__ sfeats,
    const float* __restrict__ ln_g, const float* __restrict__ ln_b,
    const float* __restrict__ w,    const float* __restrict__ bias,
    float* __restrict__ out)
{
    extern __shared__ float xs[];          // [COUT][PITCH]
    __shared__ float sw[ROWS][3];
    __shared__ int   si[ROWS][3];
    const int tid = threadIdx.x, wid = tid >> 5, lane = tid & 31;
    const int row0 = blockIdx.x * ROWS;

    if (tid < ROWS) {
        const int row = row0 + tid;
#pragma unroll
        for (int c = 0; c < 3; c++) {
            sw[tid][c] = g_wk[row * 3 + c];
            si[tid][c] = g_ik[row * 3 + c];
        }
    }

    for (int r = wid; r < ROWS; r += 6) {
        const float* x = sfeats + (size_t)(row0 + r) * COUT;
        float v[6];
        float s = 0.f, ss = 0.f;
#pragma unroll
        for (int t = 0; t < 6; t++) {
            v[t] = x[lane + 32 * t];
            s  += v[t];
            ss += v[t] * v[t];
        }
        s  = warp_sum(s);
        ss = warp_sum(ss);
        const float mu  = s * (1.0f / COUT);
        const float inv = rsqrtf(ss * (1.0f / COUT) - mu * mu + LN_EPS);
#pragma unroll
        for (int t = 0; t < 6; t++) {
            const int k = lane + 32 * t;
            xs[k * PITCH + r] = (v[t] - mu) * inv * ln_g[k] + ln_b[k];
        }
    }
    __syncthreads();

    const int j = tid;
    ull acc[ROWS / 2];
#pragma unroll
    for (int p = 0; p < ROWS / 2; p++) acc[p] = 0ull;

#pragma unroll 2
    for (int k = 0; k < COUT; k++) {
        const float wk = w[(size_t)k * COUT + j];
        const ull ww = pack2(wk, wk);
        const double2* xr = (const double2*)(xs + k * PITCH);
#pragma unroll
        for (int c = 0; c < ROWS / 4; c++) {
            const double2 d = xr[c];
            acc[2 * c]     = ffma2(__double_as_longlong(d.x), ww, acc[2 * c]);
            acc[2 * c + 1] = ffma2(__double_as_longlong(d.y), ww, acc[2 * c + 1]);
        }
    }

    const float bb = bias[j];
#pragma unroll
    for (int p = 0; p < ROWS / 2; p++) {
        float lo, hi; unpack2(acc[p], lo, hi);
#pragma unroll
        for (int hlf = 0; hlf < 2; hlf++) {
            const int r = 2 * p + hlf;
            float v = (hlf ? hi : lo) + bb;
            v = fmaf(sw[r][0], g_h[(size_t)si[r][0] * COUT + j], v);
            v = fmaf(sw[r][1], g_h[(size_t)si[r][1] * COUT + j], v);
            v = fmaf(sw[r][2], g_h[(size_t)si[r][2] * COUT + j], v);
            out[(size_t)(row0 + r) * COUT + j] = v;
        }
    }
}

// ---------------------------------------------------------------------------
__global__ void k_tail_fast(const float* __restrict__ sxyz,
                            const int* __restrict__ soff,
                            float* __restrict__ out)
{
    const int i = blockIdx.x * blockDim.x + threadIdx.x;
    const int n4 = MTOT * 3 / 4;
    const size_t base = (size_t)MTOT * COUT;
    if (i < n4) {
        ((float4*)(out + base))[i] = ((const float4*)sxyz)[i];
    } else if (i - n4 < NB) {
        out[base + (size_t)MTOT * 3 + (i - n4)] = (float)soff[i - n4];
    }
}
__global__ void k_tail_scalar(const float* __restrict__ sxyz,
                              const int* __restrict__ soff,
                              float* __restrict__ out, int extra)
{
    const int i = blockIdx.x * blockDim.x + threadIdx.x;
    if (i >= extra) return;
    const size_t base = (size_t)MTOT * COUT;
    if (i < MTOT * 3) out[base + i] = sxyz[i];
    else if (i - MTOT * 3 < NB) out[base + i] = (float)soff[i - MTOT * 3];
}

// ---------------------------------------------------------------------------
extern "C" void kernel_launch(void* const* d_in, const int* in_sizes, int n_in,
                              void* d_out, int out_size)
{
    const float* feats  = (const float*)d_in[0];
    const float* xyz    = (const float*)d_in[1];
    const float* sxyz   = (const float*)d_in[2];
    const float* sfeats = (const float*)d_in[3];
    const int*   soff   = (const int*)  d_in[5];
    const float* ln1_g  = (const float*)d_in[6];
    const float* ln1_b  = (const float*)d_in[7];
    const float* w1     = (const float*)d_in[8];
    const float* b1     = (const float*)d_in[9];
    const float* ln2_g  = (const float*)d_in[10];
    const float* ln2_b  = (const float*)d_in[11];
    const float* w2     = (const float*)d_in[12];
    const float* b2     = (const float*)d_in[13];
    float* out = (float*)d_out;

    const int smem2 = CIN  * PITCH * (int)sizeof(float);   // 104448 B
    const int smem1 = COUT * PITCH * (int)sizeof(float);   // 52224 B
    cudaFuncSetAttribute(k_ln_gemm2, cudaFuncAttributeMaxDynamicSharedMemorySize, smem2);
    cudaFuncSetAttribute(k_ln_gemm1, cudaFuncAttributeMaxDynamicSharedMemorySize, smem1);

    // order chosen so ncu -s/-c lands on a major kernel (gemm2 @4, knn @6)
    k_grid_zero<<<2, 1024>>>();
    k_grid_count<<<NTOT / 256, 256>>>(xyz);
    k_grid_scan<<<1, 1024>>>();
    k_ln_gemm2<<<NTOT / ROWS, 192, smem2>>>(feats, ln2_g, ln2_b, w2, b2);
    k_grid_scatter<<<NTOT / 256, 256>>>(xyz);
    k_knn_grid<<<MTOT / 256, 256>>>(sxyz);
    k_ln_gemm1<<<MTOT / ROWS, 192, smem1>>>(sfeats, ln1_g, ln1_b, w1, b1, out);

    const long long main_sz = (long long)MTOT * COUT;
    if ((long long)out_size > main_sz) {
        const long long extra = (long long)out_size - main_sz;
        if (extra >= (long long)MTOT * 3 + NB) {
            const int n = MTOT * 3 / 4 + NB;
            k_tail_fast<<<(n + 255) / 256, 256>>>(sxyz, soff, out);
        } else {
            k_tail_scalar<<<((int)extra + 255) / 256, 256>>>(sxyz, soff, out, (int)extra);
        }
    }
}

// round 8
// speedup vs baseline: 1.5898x; 1.5898x over previous
#include <cuda_runtime.h>
#include <math_constants.h>

#define CIN   384
#define COUT  192
#define NB    4
#define NPER  4096
#define MPER  16384
#define NTOT  (NB * NPER)   // 16384
#define MTOT  (NB * MPER)   // 65536
#define LN_EPS 1e-5f

#define GRID_R 8
#define NCELL  (GRID_R * GRID_R * GRID_R)   // 512
#define TCELL  (NB * NCELL)                 // 2048
#define CELL_H (1.0f / GRID_R)

#define ROWS   32            // rows per GEMM block
#define PITCH  36            // smem row-pitch floats (144B = 9*16B)

typedef unsigned long long ull;

// ------------------------- static device scratch ---------------------------
__device__ float  g_h [(size_t)NTOT * COUT];
__device__ float  g_wk[(size_t)MTOT * 3];
__device__ int    g_ik[(size_t)MTOT * 3];
__device__ int    g_cnt[TCELL];
__device__ int    g_cellstart[TCELL + 1];
__device__ int    g_fill[TCELL];
__device__ float4 g_pts4[NTOT];

// ------------------------- helpers -----------------------------------------
__device__ __forceinline__ float warp_sum(float v) {
#pragma unroll
    for (int o = 16; o > 0; o >>= 1) v += __shfl_xor_sync(0xffffffffu, v, o);
    return v;
}
__device__ __forceinline__ ull pack2(float lo, float hi) {
    ull r; asm("mov.b64 %0, {%1, %2};" : "=l"(r) : "f"(lo), "f"(hi)); return r;
}
__device__ __forceinline__ void unpack2(ull v, float& lo, float& hi) {
    asm("mov.b64 {%0, %1}, %2;" : "=f"(lo), "=f"(hi) : "l"(v));
}
__device__ __forceinline__ ull ffma2(ull a, ull b, ull c) {
    ull d; asm("fma.rn.f32x2 %0, %1, %2, %3;" : "=l"(d) : "l"(a), "l"(b), "l"(c)); return d;
}
__device__ __forceinline__ int cell1(float v) {
    int c = (int)(v * GRID_R);
    return min(GRID_R - 1, max(0, c));
}
__device__ __forceinline__ void ins3(float s, int gi,
                                     float& s0, float& s1, float& s2,
                                     int& i0, int& i1, int& i2) {
    if (s < s2) {
        if (s < s1) {
            s2 = s1; i2 = i1;
            if (s < s0) { s1 = s0; i1 = i0; s0 = s; i0 = gi; }
            else        { s1 = s;  i1 = gi; }
        } else { s2 = s; i2 = gi; }
    }
}
__device__ __forceinline__ void scan_run(int lo, int hi,
                                         float qx, float qy, float qz,
                                         float& s0, float& s1, float& s2,
                                         int& i0, int& i1, int& i2) {
    int j = lo;
    for (; j + 4 <= hi; j += 4) {
        const float4 p0 = g_pts4[j];
        const float4 p1 = g_pts4[j + 1];
        const float4 p2 = g_pts4[j + 2];
        const float4 p3 = g_pts4[j + 3];
        float dx, dy, dz;
        dx = qx - p0.x; dy = qy - p0.y; dz = qz - p0.z;
        const float a0 = fmaf(dx, dx, fmaf(dy, dy, dz * dz));
        dx = qx - p1.x; dy = qy - p1.y; dz = qz - p1.z;
        const float a1 = fmaf(dx, dx, fmaf(dy, dy, dz * dz));
        dx = qx - p2.x; dy = qy - p2.y; dz = qz - p2.z;
        const float a2 = fmaf(dx, dx, fmaf(dy, dy, dz * dz));
        dx = qx - p3.x; dy = qy - p3.y; dz = qz - p3.z;
        const float a3 = fmaf(dx, dx, fmaf(dy, dy, dz * dz));
        ins3(a0, __float_as_int(p0.w), s0, s1, s2, i0, i1, i2);
        ins3(a1, __float_as_int(p1.w), s0, s1, s2, i0, i1, i2);
        ins3(a2, __float_as_int(p2.w), s0, s1, s2, i0, i1, i2);
        ins3(a3, __float_as_int(p3.w), s0, s1, s2, i0, i1, i2);
    }
    for (; j < hi; j++) {
        const float4 p = g_pts4[j];
        const float dx = qx - p.x, dy = qy - p.y, dz = qz - p.z;
        const float s = fmaf(dx, dx, fmaf(dy, dy, dz * dz));
        ins3(s, __float_as_int(p.w), s0, s1, s2, i0, i1, i2);
    }
}

// ------------------------- grid build --------------------------------------
__global__ void k_grid_zero() {
    int i = blockIdx.x * 1024 + threadIdx.x;
    if (i < TCELL) g_cnt[i] = 0;
}
__global__ __launch_bounds__(256) void k_grid_count(const float* __restrict__ xyz) {
    int i = blockIdx.x * 256 + threadIdx.x;
    int b = i >> 12;
    int cx = cell1(xyz[i * 3 + 0]);
    int cy = cell1(xyz[i * 3 + 1]);
    int cz = cell1(xyz[i * 3 + 2]);
    atomicAdd(&g_cnt[b * NCELL + (cz * GRID_R + cy) * GRID_R + cx], 1);
}
__global__ __launch_bounds__(1024) void k_grid_scan() {
    __shared__ int A[TCELL], B[TCELL];
    int t = threadIdx.x;
    A[t] = g_cnt[t];  A[t + 1024] = g_cnt[t + 1024];
    __syncthreads();
    int* src = A; int* dst = B;
    for (int off = 1; off < TCELL; off <<= 1) {
        dst[t]        = src[t]        + (t        >= off ? src[t        - off] : 0);
        dst[t + 1024] = src[t + 1024] + (t + 1024 >= off ? src[t + 1024 - off] : 0);
        __syncthreads();
        int* tmp = src; src = dst; dst = tmp;
    }
    int ex0 = (t == 0) ? 0 : src[t - 1];
    g_cellstart[t] = ex0;  g_fill[t] = ex0;
    int u = t + 1024;
    int ex1 = src[u - 1];
    g_cellstart[u] = ex1;  g_fill[u] = ex1;
    if (t == 0) g_cellstart[TCELL] = NTOT;
}
__global__ __launch_bounds__(256) void k_grid_scatter(const float* __restrict__ xyz) {
    int i = blockIdx.x * 256 + threadIdx.x;
    int b = i >> 12;
    float x = xyz[i * 3 + 0], y = xyz[i * 3 + 1], z = xyz[i * 3 + 2];
    int cid = b * NCELL + (cell1(z) * GRID_R + cell1(y)) * GRID_R + cell1(x);
    int pos = atomicAdd(&g_fill[cid], 1);
    g_pts4[pos] = make_float4(x, y, z, __int_as_float(i));
}

// ------------------------- grid 3-NN ---------------------------------------
__global__ __launch_bounds__(256) void k_knn_grid(const float* __restrict__ sxyz) {
    const int q = blockIdx.x * 256 + threadIdx.x;
    const int b = q >> 14;
    const float qx = sxyz[q * 3 + 0];
    const float qy = sxyz[q * 3 + 1];
    const float qz = sxyz[q * 3 + 2];
    const int cx = cell1(qx), cy = cell1(qy), cz = cell1(qz);
    const int base = b * NCELL;

    float s0 = CUDART_INF_F, s1 = CUDART_INF_F, s2 = CUDART_INF_F;
    int   i0 = 0, i1 = 0, i2 = 0;

    {   // uniform clamped 3x3x3 pass
        const int zl = max(0, cz - 1), zh = min(GRID_R - 1, cz + 1);
        const int yl = max(0, cy - 1), yh = min(GRID_R - 1, cy + 1);
        const int xl = max(0, cx - 1), xh = min(GRID_R - 1, cx + 1);
        for (int Z = zl; Z <= zh; Z++)
            for (int Y = yl; Y <= yh; Y++) {
                const int rowb = base + (Z * GRID_R + Y) * GRID_R;
                const int lo = g_cellstart[rowb + xl];
                const int hi = g_cellstart[rowb + xh + 1];
                scan_run(lo, hi, qx, qy, qz, s0, s1, s2, i0, i1, i2);
            }
    }
    float rc = CUDART_INF_F;
    if (cx - 1 > 0)          rc = fminf(rc, qx - (cx - 1) * CELL_H);
    if (cx + 1 < GRID_R - 1) rc = fminf(rc, (cx + 2) * CELL_H - qx);
    if (cy - 1 > 0)          rc = fminf(rc, qy - (cy - 1) * CELL_H);
    if (cy + 1 < GRID_R - 1) rc = fminf(rc, (cy + 2) * CELL_H - qy);
    if (cz - 1 > 0)          rc = fminf(rc, qz - (cz - 1) * CELL_H);
    if (cz + 1 < GRID_R - 1) rc = fminf(rc, (cz + 2) * CELL_H - qz);

    if (!(s2 < rc * rc)) {
        bool done = false;
        for (int R = 2; R < GRID_R && !done; R++) {
            const int zl = max(0, cz - R), zh = min(GRID_R - 1, cz + R);
            const int yl = max(0, cy - R), yh = min(GRID_R - 1, cy + R);
            const int xl = max(0, cx - R), xh = min(GRID_R - 1, cx + R);
            for (int Z = zl; Z <= zh; Z++) {
                const bool zedge = (Z == cz - R) || (Z == cz + R);
                for (int Y = yl; Y <= yh; Y++) {
                    const bool yedge = (Y == cy - R) || (Y == cy + R);
                    const int rowb = base + (Z * GRID_R + Y) * GRID_R;
                    if (zedge || yedge) {
                        const int lo = g_cellstart[rowb + xl];
                        const int hi = g_cellstart[rowb + xh + 1];
                        scan_run(lo, hi, qx, qy, qz, s0, s1, s2, i0, i1, i2);
                    } else {
#pragma unroll
                        for (int e = 0; e < 2; e++) {
                            const int X = (e == 0) ? (cx - R) : (cx + R);
                            if (X < 0 || X >= GRID_R) continue;
                            const int lo = g_cellstart[rowb + X];
                            const int hi = g_cellstart[rowb + X + 1];
                            scan_run(lo, hi, qx, qy, qz, s0, s1, s2, i0, i1, i2);
                        }
                    }
                }
            }
            float rcv = CUDART_INF_F;
            if (cx - R > 0)          rcv = fminf(rcv, qx - (cx - R) * CELL_H);
            if (cx + R < GRID_R - 1) rcv = fminf(rcv, (cx + R + 1) * CELL_H - qx);
            if (cy - R > 0)          rcv = fminf(rcv, qy - (cy - R) * CELL_H);
            if (cy + R < GRID_R - 1) rcv = fminf(rcv, (cy + R + 1) * CELL_H - qy);
            if (cz - R > 0)          rcv = fminf(rcv, qz - (cz - R) * CELL_H);
            if (cz + R < GRID_R - 1) rcv = fminf(rcv, (cz + R + 1) * CELL_H - qz);
            if (s2 < rcv * rcv) done = true;
        }
    }

    const float d0 = sqrtf(fmaxf(s0, 0.f));
    const float d1 = sqrtf(fmaxf(s1, 0.f));
    const float d2 = sqrtf(fmaxf(s2, 0.f));
    const float r0 = 1.0f / (d0 + 1e-8f);
    const float r1 = 1.0f / (d1 + 1e-8f);
    const float r2 = 1.0f / (d2 + 1e-8f);
    const float rs = 1.0f / (r0 + r1 + r2);
    g_wk[q * 3 + 0] = r0 * rs;  g_ik[q * 3 + 0] = i0;
    g_wk[q * 3 + 1] = r1 * rs;  g_ik[q * 3 + 1] = i1;
    g_wk[q * 3 + 2] = r2 * rs;  g_ik[q * 3 + 2] = i2;
}

// ---------------------------------------------------------------------------
// GEMM 2: h = LN(feats; ln2) @ w2 + b2
// 192 threads, 32 rows/block; thread tile TM=8 x TN=4 (f32x2 row pairs)
// ---------------------------------------------------------------------------
__global__ __launch_bounds__(192) void k_ln_gemm2(
    const float* __restrict__ feats,
    const float* __restrict__ ln_g, const float* __restrict__ ln_b,
    const float* __restrict__ w,    const float* __restrict__ bias)
{
    extern __shared__ float xs[];          // [CIN][PITCH]
    const int tid = threadIdx.x, wid = tid >> 5, lane = tid & 31;
    const int row0 = blockIdx.x * ROWS;

    for (int r = wid; r < ROWS; r += 6) {
        const float* x = feats + (size_t)(row0 + r) * CIN;
        float v[12];
        float s = 0.f, ss = 0.f;
#pragma unroll
        for (int t = 0; t < 12; t++) {
            v[t] = x[lane + 32 * t];
            s  += v[t];
            ss += v[t] * v[t];
        }
        s  = warp_sum(s);
        ss = warp_sum(ss);
        const float mu  = s * (1.0f / CIN);
        const float inv = rsqrtf(ss * (1.0f / CIN) - mu * mu + LN_EPS);
#pragma unroll
        for (int t = 0; t < 12; t++) {
            const int k = lane + 32 * t;
            xs[k * PITCH + r] = (v[t] - mu) * inv * ln_g[k] + ln_b[k];
        }
    }
    __syncthreads();

    const int cg = tid % 48, rg = tid / 48;   // 48 col-groups x 4 row-groups
    const int c0 = cg * 4, r0 = rg * 8;

    ull acc[16];
#pragma unroll
    for (int i = 0; i < 16; i++) acc[i] = 0ull;

#pragma unroll 4
    for (int k = 0; k < CIN; k++) {
        const float4 wv = *reinterpret_cast<const float4*>(w + (size_t)k * COUT + c0);
        ull wp[4];
        wp[0] = pack2(wv.x, wv.x);  wp[1] = pack2(wv.y, wv.y);
        wp[2] = pack2(wv.z, wv.z);  wp[3] = pack2(wv.w, wv.w);
        const double2* xr = (const double2*)(xs + k * PITCH + r0);
        const double2 xa = xr[0], xb = xr[1];
        ull xp[4];
        xp[0] = __double_as_longlong(xa.x);  xp[1] = __double_as_longlong(xa.y);
        xp[2] = __double_as_longlong(xb.x);  xp[3] = __double_as_longlong(xb.y);
#pragma unroll
        for (int p = 0; p < 4; p++)
#pragma unroll
            for (int c = 0; c < 4; c++)
                acc[p * 4 + c] = ffma2(xp[p], wp[c], acc[p * 4 + c]);
    }

    const float4 bb = *reinterpret_cast<const float4*>(bias + c0);
#pragma unroll
    for (int p = 0; p < 4; p++) {
        float lo[4], hi[4];
#pragma unroll
        for (int c = 0; c < 4; c++) unpack2(acc[p * 4 + c], lo[c], hi[c]);
        const int rlo = row0 + r0 + 2 * p;
        float4 v0 = make_float4(lo[0] + bb.x, lo[1] + bb.y, lo[2] + bb.z, lo[3] + bb.w);
        float4 v1 = make_float4(hi[0] + bb.x, hi[1] + bb.y, hi[2] + bb.z, hi[3] + bb.w);
        *reinterpret_cast<float4*>(g_h + (size_t)rlo       * COUT + c0) = v0;
        *reinterpret_cast<float4*>(g_h + (size_t)(rlo + 1) * COUT + c0) = v1;
    }
}

// ---------------------------------------------------------------------------
// GEMM 1: out = LN(support_feats; ln1) @ w1 + b1 + interp-gather(g_h)
// ---------------------------------------------------------------------------
__global__ __launch_bounds__(192) void k_ln_gemm1(
    const float* __restrict__ sfeats,
    const float* __restrict__ ln_g, const float* __restrict__ ln_b,
    const float* __restrict__ w,    const float* __restrict__ bias,
    float* __restrict__ out)
{
    extern __shared__ float xs[];          // [COUT][PITCH]
    __shared__ float sw[ROWS][3];
    __shared__ int   si[ROWS][3];
    const int tid = threadIdx.x, wid = tid >> 5, lane = tid & 31;
    const int row0 = blockIdx.x * ROWS;

    if (tid < ROWS) {
        const int row = row0 + tid;
#pragma unroll
        for (int c = 0; c < 3; c++) {
            sw[tid][c] = g_wk[row * 3 + c];
            si[tid][c] = g_ik[row * 3 + c];
        }
    }

    for (int r = wid; r < ROWS; r += 6) {
        const float* x = sfeats + (size_t)(row0 + r) * COUT;
        float v[6];
        float s = 0.f, ss = 0.f;
#pragma unroll
        for (int t = 0; t < 6; t++) {
            v[t] = x[lane + 32 * t];
            s  += v[t];
            ss += v[t] * v[t];
        }
        s  = warp_sum(s);
        ss = warp_sum(ss);
        const float mu  = s * (1.0f / COUT);
        const float inv = rsqrtf(ss * (1.0f / COUT) - mu * mu + LN_EPS);
#pragma unroll
        for (int t = 0; t < 6; t++) {
            const int k = lane + 32 * t;
            xs[k * PITCH + r] = (v[t] - mu) * inv * ln_g[k] + ln_b[k];
        }
    }
    __syncthreads();

    const int cg = tid % 48, rg = tid / 48;
    const int c0 = cg * 4, r0 = rg * 8;

    ull acc[16];
#pragma unroll
    for (int i = 0; i < 16; i++) acc[i] = 0ull;

#pragma unroll 4
    for (int k = 0; k < COUT; k++) {
        const float4 wv = *reinterpret_cast<const float4*>(w + (size_t)k * COUT + c0);
        ull wp[4];
        wp[0] = pack2(wv.x, wv.x);  wp[1] = pack2(wv.y, wv.y);
        wp[2] = pack2(wv.z, wv.z);  wp[3] = pack2(wv.w, wv.w);
        const double2* xr = (const double2*)(xs + k * PITCH + r0);
        const double2 xa = xr[0], xb = xr[1];
        ull xp[4];
        xp[0] = __double_as_longlong(xa.x);  xp[1] = __double_as_longlong(xa.y);
        xp[2] = __double_as_longlong(xb.x);  xp[3] = __double_as_longlong(xb.y);
#pragma unroll
        for (int p = 0; p < 4; p++)
#pragma unroll
            for (int c = 0; c < 4; c++)
                acc[p * 4 + c] = ffma2(xp[p], wp[c], acc[p * 4 + c]);
    }

    const float4 bb = *reinterpret_cast<const float4*>(bias + c0);
#pragma unroll
    for (int p = 0; p < 4; p++) {
        float lo[4], hi[4];
#pragma unroll
        for (int c = 0; c < 4; c++) unpack2(acc[p * 4 + c], lo[c], hi[c]);
#pragma unroll
        for (int hlf = 0; hlf < 2; hlf++) {
            const int r = r0 + 2 * p + hlf;
            const float* a = hlf ? hi : lo;
            float4 v = make_float4(a[0] + bb.x, a[1] + bb.y, a[2] + bb.z, a[3] + bb.w);
#pragma unroll
            for (int nn = 0; nn < 3; nn++) {
                const float wgt = sw[r][nn];
                const float4 hh = *reinterpret_cast<const float4*>(
                    g_h + (size_t)si[r][nn] * COUT + c0);
                v.x = fmaf(wgt, hh.x, v.x);
                v.y = fmaf(wgt, hh.y, v.y);
                v.z = fmaf(wgt, hh.z, v.z);
                v.w = fmaf(wgt, hh.w, v.w);
            }
            *reinterpret_cast<float4*>(out + (size_t)(row0 + r) * COUT + c0) = v;
        }
    }
}

// ---------------------------------------------------------------------------
__global__ void k_tail_fast(const float* __restrict__ sxyz,
                            const int* __restrict__ soff,
                            float* __restrict__ out)
{
    const int i = blockIdx.x * blockDim.x + threadIdx.x;
    const int n4 = MTOT * 3 / 4;
    const size_t base = (size_t)MTOT * COUT;
    if (i < n4) {
        ((float4*)(out + base))[i] = ((const float4*)sxyz)[i];
    } else if (i - n4 < NB) {
        out[base + (size_t)MTOT * 3 + (i - n4)] = (float)soff[i - n4];
    }
}
__global__ void k_tail_scalar(const float* __restrict__ sxyz,
                              const int* __restrict__ soff,
                              float* __restrict__ out, int extra)
{
    const int i = blockIdx.x * blockDim.x + threadIdx.x;
    if (i >= extra) return;
    const size_t base = (size_t)MTOT * COUT;
    if (i < MTOT * 3) out[base + i] = sxyz[i];
    else if (i - MTOT * 3 < NB) out[base + i] = (float)soff[i - MTOT * 3];
}

// ---------------------------------------------------------------------------
extern "C" void kernel_launch(void* const* d_in, const int* in_sizes, int n_in,
                              void* d_out, int out_size)
{
    const float* feats  = (const float*)d_in[0];
    const float* xyz    = (const float*)d_in[1];
    const float* sxyz   = (const float*)d_in[2];
    const float* sfeats = (const float*)d_in[3];
    const int*   soff   = (const int*)  d_in[5];
    const float* ln1_g  = (const float*)d_in[6];
    const float* ln1_b  = (const float*)d_in[7];
    const float* w1     = (const float*)d_in[8];
    const float* b1     = (const float*)d_in[9];
    const float* ln2_g  = (const float*)d_in[10];
    const float* ln2_b  = (const float*)d_in[11];
    const float* w2     = (const float*)d_in[12];
    const float* b2     = (const float*)d_in[13];
    float* out = (float*)d_out;

    const int smem2 = CIN  * PITCH * (int)sizeof(float);   // 55296 B
    const int smem1 = COUT * PITCH * (int)sizeof(float);   // 27648 B
    cudaFuncSetAttribute(k_ln_gemm2, cudaFuncAttributeMaxDynamicSharedMemorySize, smem2);
    cudaFuncSetAttribute(k_ln_gemm1, cudaFuncAttributeMaxDynamicSharedMemorySize, smem1);

    k_grid_zero<<<2, 1024>>>();
    k_grid_count<<<NTOT / 256, 256>>>(xyz);
    k_grid_scan<<<1, 1024>>>();
    k_ln_gemm2<<<NTOT / ROWS, 192, smem2>>>(feats, ln2_g, ln2_b, w2, b2);
    k_grid_scatter<<<NTOT / 256, 256>>>(xyz);
    k_knn_grid<<<MTOT / 256, 256>>>(sxyz);
    k_ln_gemm1<<<MTOT / ROWS, 192, smem1>>>(sfeats, ln1_g, ln1_b, w1, b1, out);

    const long long main_sz = (long long)MTOT * COUT;
    if ((long long)out_size > main_sz) {
        const long long extra = (long long)out_size - main_sz;
        if (extra >= (long long)MTOT * 3 + NB) {
            const int n = MTOT * 3 / 4 + NB;
            k_tail_fast<<<(n + 255) / 256, 256>>>(sxyz, soff, out);
        } else {
            k_tail_scalar<<<((int)extra + 255) / 256, 256>>>(sxyz, soff, out, (int)extra);
        }
    }
}